// round 2
// baseline (speedup 1.0000x reference)
#include <cuda_runtime.h>
#include <cstdint>

#define B        4
#define T        1024
#define HALF     256      // VALUE_DIM / 2
#define C        256
#define NLAB     64
#define VDIM     512

#define NBLK     256      // grid size (must be co-resident for the barrier)
#define NTHR     256

// Scratch: A[b][l][d]  (B * NLAB * HALF floats = 65536)
// Invariant: zero at entry to every launch (static zero-init + consume-and-clear
// in the contract phase of the previous launch).
__device__ float g_A[B * NLAB * HALF];

// Sense-reversing grid barrier state (persists across graph replays; the
// sense monotonically increments one step per launch, count self-resets).
__device__ unsigned int          g_bar_count;
__device__ volatile unsigned int g_bar_sense;

__device__ __forceinline__ void grid_barrier() {
    __syncthreads();
    __threadfence();                       // publish scatter atomics / out zeros
    if (threadIdx.x == 0) {
        unsigned int sense = g_bar_sense;  // stable: can't flip until all arrive
        unsigned int t = atomicAdd(&g_bar_count, 1u);
        if (t == gridDim.x - 1u) {
            atomicExch(&g_bar_count, 0u);  // reset in atomic domain
            __threadfence();
            g_bar_sense = sense + 1u;      // release
        } else {
            while (g_bar_sense == sense) { }
        }
    }
    __syncthreads();
    __threadfence();                       // acquire side
}

// ---------------------------------------------------------------------------
// Fused kernel: [zero out] + scatter  ||barrier||  contract + clear-A
// ---------------------------------------------------------------------------
__global__ void __launch_bounds__(NTHR)
vb_fused_kernel(const int*   __restrict__ indices,
                const float* __restrict__ scores,
                const float* __restrict__ W,
                const int*   __restrict__ label,
                const int*   __restrict__ index_p,
                const float* __restrict__ weight,
                float*       __restrict__ out) {
    const int tid = threadIdx.x;
    const int bid = blockIdx.x;
    const int off = (*index_p == 1) ? HALF : 0;

    // --- zero the output (poisoned by harness each replay) ------------------
    if (bid < B) out[bid * C + tid] = 0.0f;

    // --- Phase 1: scatter-accumulate ----------------------------------------
    //   A[b, label[b,t], d] += score[b,t] * weight[idx[b,t], off + d]
    // 256 blocks * 8 warps = 2048 warps; 2 tokens per warp.
    {
        const int gw   = bid * (NTHR / 32) + (tid >> 5);
        const int lane = tid & 31;
#pragma unroll
        for (int r = 0; r < 2; r++) {
            const int tok = gw * 2 + r;            // 0 .. B*T-1
            const int   idx = indices[tok];        // warp-uniform broadcast
            const float sc  = scores[tok];
            const int   lab = label[tok];
            const int   b   = tok >> 10;           // tok = b*T + t

            const float4* wrow = reinterpret_cast<const float4*>(
                weight + (size_t)idx * VDIM + off);
            float4 v0 = __ldg(wrow + lane);
            float4 v1 = __ldg(wrow + lane + 32);
            v0.x *= sc; v0.y *= sc; v0.z *= sc; v0.w *= sc;
            v1.x *= sc; v1.y *= sc; v1.z *= sc; v1.w *= sc;

            float4* dst = reinterpret_cast<float4*>(
                g_A + (size_t)(b * NLAB + lab) * HALF);
            atomicAdd(dst + lane,      v0);
            atomicAdd(dst + lane + 32, v1);
        }
    }

    grid_barrier();

    // --- Phase 2: contraction  out[b,c] += sum_{d in chunk} A[b,l,d]*W[l,off+d,c]
    // Block (l, ch): l = bid>>2, ch = bid&3 (d-chunk of 64).
    __shared__ float sA[B][64];
    const int l  = bid >> 2;
    const int ch = bid & 3;
    {
        const int b  = tid >> 6;
        const int dd = tid & 63;
        float* ap = &g_A[(size_t)(b * NLAB + l) * HALF + ch * 64 + dd];
        sA[b][dd] = __ldcg(ap);   // L2 load: sees the scatter atomics
        *ap = 0.0f;               // consume-and-clear: zero for next replay
    }
    __syncthreads();

    const float* Wbase = W + ((size_t)l * VDIM + off + ch * 64) * C + tid;

    float a0 = 0.f, a1 = 0.f, a2 = 0.f, a3 = 0.f;
#pragma unroll
    for (int d = 0; d < 64; d++) {
        float w = __ldg(Wbase + (size_t)d * C);   // coalesced across c
        a0 += sA[0][d] * w;
        a1 += sA[1][d] * w;
        a2 += sA[2][d] * w;
        a3 += sA[3][d] * w;
    }

    atomicAdd(out + 0 * C + tid, a0);
    atomicAdd(out + 1 * C + tid, a1);
    atomicAdd(out + 2 * C + tid, a2);
    atomicAdd(out + 3 * C + tid, a3);
}

// ---------------------------------------------------------------------------
// Inputs (metadata order):
//   0: indices (B,T) int32     1: scores (B,T) f32
//   2: W (64,512,256) f32      3: label (B,T) int32
//   4: index scalar int32      5: weight (262144,512) f32
// Output: (B, C) f32 = 1024 floats
// ---------------------------------------------------------------------------
extern "C" void kernel_launch(void* const* d_in, const int* in_sizes, int n_in,
                              void* d_out, int out_size) {
    const int*   indices = (const int*)  d_in[0];
    const float* scores  = (const float*)d_in[1];
    const float* W       = (const float*)d_in[2];
    const int*   label   = (const int*)  d_in[3];
    const int*   index_p = (const int*)  d_in[4];
    const float* weight  = (const float*)d_in[5];
    float*       out     = (float*)d_out;

    vb_fused_kernel<<<NBLK, NTHR>>>(indices, scores, W, label, index_p,
                                    weight, out);
}